// round 7
// baseline (speedup 1.0000x reference)
#include <cuda_runtime.h>
#include <cuda_bf16.h>
#include <math.h>

// Fixed shapes: cls_conv_out (4, 1029, 100, 100) fp32; rois (2000,4) int32.
// Only batch 3 used. Output (2000, 21, 1, 1) fp32.
#define KK       7
#define C1       21
#define NJL      49
#define H        100
#define W        100
#define HP       101
#define ROW_S    2124                 // HP*C1=2121 padded to mult of 4 (16B-aligned rows)
#define ROW4     (ROW_S / 4)          // 531 float4 per row
#define PLANE_S  (HP * ROW_S)
#define IN_BASE  (3 * 1029 * 10000)   // batch 3 offset

// Integral image, transposed c-innermost: I[jl][y][x][c]; ~42 MB scratch.
__device__ float g_integral[(size_t)NJL * PLANE_S];

// ---------------------------------------------------------------------------
// Kernel A: per (jl, 2 y-rows): float4 global loads for BOTH rows up front
// (MLP), register shuffle-scan x-cumsum per channel, smem stage, then
// float4 transposed stores (531 STG.128 per row instead of 2121 STG.32).
// ---------------------------------------------------------------------------
__global__ void __launch_bounds__(128) build_xsum(const float* __restrict__ in) {
    const int y0   = 2 * blockIdx.x + 1;  // first row: 1,3,..,99
    const int jl   = blockIdx.y;          // 0..48
    const int t    = threadIdx.x;
    const int w    = t >> 5, lane = t & 31;

    __shared__ float sm[2][C1 * HP];      // sm[r][c*101 + x], inclusive cumsum

    // --- load both rows: warp w owns channels {w, w+4, ...}; lanes 0..24
    const float4* base4 = (const float4*)(in + IN_BASE + (size_t)jl * (C1 * H * W));
    float4 v0[6], v1[6];
    #pragma unroll
    for (int k = 0; k < 6; k++) {
        const int c = w + 4 * k;
        if (c < C1 && lane < 25) {
            const int co = c * (H * W / 4);
            v0[k] = base4[co + (y0 - 1) * (W / 4) + lane];
            v1[k] = base4[co + (y0)     * (W / 4) + lane];
        }
    }

    // --- scan each owned channel for both rows
    #pragma unroll
    for (int r = 0; r < 2; r++) {
        #pragma unroll
        for (int k = 0; k < 6; k++) {
            const int c = w + 4 * k;
            if (c < C1) {
                float4 vv = (r == 0) ? v0[k] : v1[k];
                float s0 = vv.x;
                float s1 = s0 + vv.y;
                float s2 = s1 + vv.z;
                float s3 = s2 + vv.w;
                float run = s3;
                #pragma unroll
                for (int d = 1; d < 32; d <<= 1) {
                    float u = __shfl_up_sync(0xffffffffu, run, d);
                    if (lane >= d) run += u;
                }
                const float off = run - s3;
                if (lane < 25) {
                    float* dst = sm[r] + c * HP + 4 * lane;
                    dst[0] = off + s0; dst[1] = off + s1;
                    dst[2] = off + s2; dst[3] = off + s3;
                }
            }
        }
    }
    __syncthreads();

    // --- transposed float4 stores, incremental (x,c) bookkeeping.
    // element e = 4*i4 + j maps to x = e/21, c = e%21; output value is
    // 0 for x==0, cumsum[x-1] otherwise.  e advances by 512 per iteration:
    // x += 24, c += 8 (wrap).  xx in [1,100] valid, else 0 (covers padding).
    float* out0 = g_integral + ((size_t)jl * HP + y0) * ROW_S;
    float* out1 = out0 + ROW_S;
    {
        int e = 4 * t;
        int x = e / C1, c = e - x * C1;
        for (int i4 = t; i4 < ROW4; i4 += 128) {
            float4 f0, f1;
            int xx = x, cc = c;
            float* r0;
            float* r1;
            #define GET(FIELD)                                                 \
                r0 = sm[0] + cc * HP; r1 = sm[1] + cc * HP;                    \
                f0.FIELD = ((unsigned)(xx - 1) < 100u) ? r0[xx - 1] : 0.0f;    \
                f1.FIELD = ((unsigned)(xx - 1) < 100u) ? r1[xx - 1] : 0.0f;    \
                if (++cc == C1) { cc = 0; ++xx; }
            GET(x) GET(y) GET(z) GET(w)
            #undef GET
            ((float4*)out0)[i4] = f0;
            ((float4*)out1)[i4] = f1;
            x += 24; c += 8;
            if (c >= C1) { c -= C1; ++x; }
        }
    }
}

// ---------------------------------------------------------------------------
// Kernel B: y-cumsum over float4 slots (531/row). Writes y=0 zero row, then
// 100 dependent FADD4 steps; unroll 10 for in-flight load MLP.
// ---------------------------------------------------------------------------
__global__ void build_ysum() {
    const int jl    = blockIdx.y;
    const int slot4 = blockIdx.x * blockDim.x + threadIdx.x;
    if (slot4 >= ROW4) return;

    float4* p = (float4*)(g_integral + (size_t)jl * PLANE_S) + slot4;

    float4 acc = make_float4(0.f, 0.f, 0.f, 0.f);
    p[0] = acc;                         // y = 0 row is zero
    #pragma unroll 10
    for (int y = 1; y <= H; y++) {
        float4 v = p[(size_t)y * ROW4];
        acc.x += v.x; acc.y += v.y; acc.z += v.z; acc.w += v.w;
        p[(size_t)y * ROW4] = acc;
    }
}

// ---------------------------------------------------------------------------
// Kernel C: one block per ROI. 336 active threads (16 jl-groups x 21 c),
// div-free mapping; 4 corner reads per (jl,c); deterministic reduction;
// warp softmax.
// ---------------------------------------------------------------------------
__global__ void pool_softmax(const int* __restrict__ rois,
                             float* __restrict__ out) {
    const int roi = blockIdx.x;
    const int t   = threadIdx.x;
    __shared__ float s_S[NJL * C1];
    __shared__ float s_avg[C1];

    const int4 r = ((const int4*)rois)[roi];   // ymin, xmin, ymax, xmax
    const int ys = (r.z - r.x) / KK;
    const int xs = (r.w - r.y) / KK;

    if (t < 336) {
        const int c   = t % C1;
        const int jl0 = t / C1;   // 0..15
        #pragma unroll
        for (int jl = jl0; jl < NJL; jl += 16) {
            const int j = jl / KK, l = jl - j * KK;
            const int y0 = r.x + j * ys, y1 = y0 + ys;
            const int x0 = r.y + l * xs, x1 = x0 + xs;
            const float* P = g_integral + (size_t)jl * PLANE_S;
            const float a = P[(size_t)y1 * ROW_S + x1 * C1 + c];
            const float b = P[(size_t)y0 * ROW_S + x1 * C1 + c];
            const float d = P[(size_t)y1 * ROW_S + x0 * C1 + c];
            const float e = P[(size_t)y0 * ROW_S + x0 * C1 + c];
            s_S[jl * C1 + c] = (a - b) - (d - e);
        }
    }
    __syncthreads();

    if (t < C1) {
        float acc = 0.0f;
        #pragma unroll 7
        for (int jl = 0; jl < NJL; jl++) acc += s_S[jl * C1 + t];
        s_avg[t] = acc / (49.0f * (float)(ys * xs));
    }
    __syncthreads();

    if (t < 32) {
        const bool act = t < C1;
        float v = act ? s_avg[t] : -INFINITY;
        float m = v;
        #pragma unroll
        for (int o = 16; o; o >>= 1) m = fmaxf(m, __shfl_xor_sync(0xffffffffu, m, o));
        float e = act ? expf(v - m) : 0.0f;
        float sum = e;
        #pragma unroll
        for (int o = 16; o; o >>= 1) sum += __shfl_xor_sync(0xffffffffu, sum, o);
        if (act) out[(size_t)roi * C1 + t] = e / sum;
    }
}

// ---------------------------------------------------------------------------
extern "C" void kernel_launch(void* const* d_in, const int* in_sizes, int n_in,
                              void* d_out, int out_size) {
    const float* x    = (const float*)d_in[0];
    const int*   rois = (const int*)d_in[1];
    float*       out  = (float*)d_out;
    const int n_rois  = in_sizes[1] / 4;   // 2000

    dim3 gA(H / 2, NJL);                    // 50 x 49, 2 rows per block
    build_xsum<<<gA, 128>>>(x);

    dim3 gB((ROW4 + 127) / 128, NJL);       // 5 x 49
    build_ysum<<<gB, 128>>>();

    pool_softmax<<<n_rois, 352>>>(rois, out);
}